// round 1
// baseline (speedup 1.0000x reference)
#include <cuda_runtime.h>
#include <math.h>

#define D 4096
#define NK 24                 // 16 res + 4 pre + 4 post logits per token
#define NTOK_MAX 16384
#define TAU_INV 10.0f
#define RMS_EPS 1.1920929e-07f

// Scratch (no cudaMalloc allowed): logits laid out [k][token] for coalesced
// reads in the sinkhorn kernel; M laid out [token][16] for broadcast reads in mix.
__device__ float g_logits[(NK + 1) * NTOK_MAX];
__device__ float g_M[NTOK_MAX * 16];

__device__ __forceinline__ float warpSum(float v) {
    v += __shfl_xor_sync(0xffffffffu, v, 16);
    v += __shfl_xor_sync(0xffffffffu, v, 8);
    v += __shfl_xor_sync(0xffffffffu, v, 4);
    v += __shfl_xor_sync(0xffffffffu, v, 2);
    v += __shfl_xor_sync(0xffffffffu, v, 1);
    return v;
}

// ---------------------------------------------------------------------------
// Kernel A: per-token 24 raw dot products + sum of squares.
// CTA = 256 threads (8 warps), 16 tokens per CTA (2 per warp).
// W staged in smem in 512-float chunks (24 x 512 x 4B = 48KB) so each W value
// is reused across all 16 tokens of the CTA (W L2 traffic ~= 400MB total).
// ---------------------------------------------------------------------------
__global__ __launch_bounds__(256) void logits_kernel(
    const float* __restrict__ x,
    const float* __restrict__ Wres,
    const float* __restrict__ Wpre,
    const float* __restrict__ Wpost,
    int NT)
{
    __shared__ float4 Wch[NK * 128];  // 24 rows x 128 float4 (512 floats) = 48KB

    const int tid  = threadIdx.x;
    const int lane = tid & 31;
    const int warp = tid >> 5;
    const int t0   = blockIdx.x * 16 + warp * 2;
    const int t1   = t0 + 1;

    const float4* xr0 = reinterpret_cast<const float4*>(x + (size_t)t0 * D);
    const float4* xr1 = reinterpret_cast<const float4*>(x + (size_t)t1 * D);

    float acc0[NK], acc1[NK];
    float ss0 = 0.0f, ss1 = 0.0f;
#pragma unroll
    for (int k = 0; k < NK; ++k) { acc0[k] = 0.0f; acc1[k] = 0.0f; }

    for (int chunk = 0; chunk < D; chunk += 512) {
        // Cooperative load of the 24 x 512 W chunk into smem (float4, coalesced per row).
        for (int i = tid; i < NK * 128; i += 256) {
            int k = i >> 7;          // which of the 24 weight rows
            int p = i & 127;         // float4 index within chunk
            const float* wrow;
            if (k < 16)      wrow = Wres  + (size_t)k * D;
            else if (k < 20) wrow = Wpre  + (size_t)(k - 16) * D;
            else             wrow = Wpost + (size_t)(k - 20) * D;
            Wch[i] = reinterpret_cast<const float4*>(wrow)[(chunk >> 2) + p];
        }
        __syncthreads();

#pragma unroll
        for (int s = 0; s < 4; ++s) {
            int idx4 = (chunk >> 2) + s * 32 + lane;
            float4 a0 = xr0[idx4];
            float4 a1 = xr1[idx4];
            ss0 = fmaf(a0.x, a0.x, fmaf(a0.y, a0.y, fmaf(a0.z, a0.z, fmaf(a0.w, a0.w, ss0))));
            ss1 = fmaf(a1.x, a1.x, fmaf(a1.y, a1.y, fmaf(a1.z, a1.z, fmaf(a1.w, a1.w, ss1))));
#pragma unroll
            for (int k = 0; k < NK; ++k) {
                float4 w = Wch[k * 128 + s * 32 + lane];
                acc0[k] = fmaf(w.x, a0.x, fmaf(w.y, a0.y, fmaf(w.z, a0.z, fmaf(w.w, a0.w, acc0[k]))));
                acc1[k] = fmaf(w.x, a1.x, fmaf(w.y, a1.y, fmaf(w.z, a1.z, fmaf(w.w, a1.w, acc1[k]))));
            }
        }
        __syncthreads();
    }

    // Warp-level reduction of all accumulators; lane 0 stores.
#pragma unroll
    for (int k = 0; k < NK; ++k) { acc0[k] = warpSum(acc0[k]); acc1[k] = warpSum(acc1[k]); }
    ss0 = warpSum(ss0);
    ss1 = warpSum(ss1);

    if (lane == 0) {
#pragma unroll
        for (int k = 0; k < NK; ++k) {
            g_logits[(size_t)k * NT + t0] = acc0[k];
            g_logits[(size_t)k * NT + t1] = acc1[k];
        }
        g_logits[(size_t)NK * NT + t0] = ss0;
        g_logits[(size_t)NK * NT + t1] = ss1;
    }
}

// ---------------------------------------------------------------------------
// Kernel A2: per-token RMS scale, Sinkhorn(50 iters, log domain, max-sub),
// softmaxes, gate; emits combined 4x4 mixing matrix M.
// ---------------------------------------------------------------------------
__global__ __launch_bounds__(128) void sinkhorn_kernel(
    const float* __restrict__ HresB,
    const float* __restrict__ HpreB,
    const float* __restrict__ HpostB,
    const float* __restrict__ gate,
    int NT)
{
    int t = blockIdx.x * 128 + threadIdx.x;
    if (t >= NT) return;

    float ss  = g_logits[(size_t)NK * NT + t];
    float rms = rsqrtf(ss * (1.0f / (float)D) + RMS_EPS);

    float Z[16];
#pragma unroll
    for (int ij = 0; ij < 16; ++ij)
        Z[ij] = (HresB[ij] + g_logits[(size_t)ij * NT + t] * rms) * TAU_INV;

    float pre[4], post[4];
#pragma unroll
    for (int i = 0; i < 4; ++i) {
        pre[i]  = HpreB[i]  + g_logits[(size_t)(16 + i) * NT + t] * rms;
        post[i] = HpostB[i] + g_logits[(size_t)(20 + i) * NT + t] * rms;
    }

    float u[4] = {0.f, 0.f, 0.f, 0.f};
    float v[4] = {0.f, 0.f, 0.f, 0.f};
#pragma unroll 1
    for (int it = 0; it < 50; ++it) {
#pragma unroll
        for (int i = 0; i < 4; ++i) {
            float a0 = Z[i * 4 + 0] + v[0];
            float a1 = Z[i * 4 + 1] + v[1];
            float a2 = Z[i * 4 + 2] + v[2];
            float a3 = Z[i * 4 + 3] + v[3];
            float m = fmaxf(fmaxf(a0, a1), fmaxf(a2, a3));
            float s = expf(a0 - m) + expf(a1 - m) + expf(a2 - m) + expf(a3 - m);
            u[i] = -(m + logf(s));
        }
#pragma unroll
        for (int j = 0; j < 4; ++j) {
            float a0 = Z[0 * 4 + j] + u[0];
            float a1 = Z[1 * 4 + j] + u[1];
            float a2 = Z[2 * 4 + j] + u[2];
            float a3 = Z[3 * 4 + j] + u[3];
            float m = fmaxf(fmaxf(a0, a1), fmaxf(a2, a3));
            float s = expf(a0 - m) + expf(a1 - m) + expf(a2 - m) + expf(a3 - m);
            v[j] = -(m + logf(s));
        }
    }

    // softmax(pre), softmax(post) with max subtraction
    {
        float m = fmaxf(fmaxf(pre[0], pre[1]), fmaxf(pre[2], pre[3]));
        float e0 = expf(pre[0] - m), e1 = expf(pre[1] - m), e2 = expf(pre[2] - m), e3 = expf(pre[3] - m);
        float inv = 1.0f / (e0 + e1 + e2 + e3);
        pre[0] = e0 * inv; pre[1] = e1 * inv; pre[2] = e2 * inv; pre[3] = e3 * inv;
    }
    {
        float m = fmaxf(fmaxf(post[0], post[1]), fmaxf(post[2], post[3]));
        float e0 = expf(post[0] - m), e1 = expf(post[1] - m), e2 = expf(post[2] - m), e3 = expf(post[3] - m);
        float inv = 1.0f / (e0 + e1 + e2 + e3);
        post[0] = e0 * inv; post[1] = e1 * inv; post[2] = e2 * inv; post[3] = e3 * inv;
    }

    float g = 1.0f / (1.0f + expf(-gate[0]));
    float M[16];
#pragma unroll
    for (int i = 0; i < 4; ++i) {
#pragma unroll
        for (int j = 0; j < 4; ++j) {
            float hres = expf(Z[i * 4 + j] + u[i] + v[j]);
            float mg   = g * hres + ((i == j) ? (1.0f - g) : 0.0f);
            M[i * 4 + j] = mg + post[i] * pre[j];
        }
    }

    float4* mp = reinterpret_cast<float4*>(g_M + (size_t)t * 16);
    mp[0] = make_float4(M[0],  M[1],  M[2],  M[3]);
    mp[1] = make_float4(M[4],  M[5],  M[6],  M[7]);
    mp[2] = make_float4(M[8],  M[9],  M[10], M[11]);
    mp[3] = make_float4(M[12], M[13], M[14], M[15]);
}

// ---------------------------------------------------------------------------
// Kernel B: out_row = M @ x_streams. One CTA per token, 256 threads,
// each thread handles 4 columns via float4. Pure streaming (512MB total).
// ---------------------------------------------------------------------------
__global__ __launch_bounds__(256) void mix_kernel(
    const float* __restrict__ x,
    float* __restrict__ out)
{
    const int t = blockIdx.x;
    const float4* Mr = reinterpret_cast<const float4*>(g_M + (size_t)t * 16);
    const float4 m0 = Mr[0];
    const float4 m1 = Mr[1];
    const float4 m2 = Mr[2];
    const float4 m3 = Mr[3];

    const float4* xr = reinterpret_cast<const float4*>(x + (size_t)t * D);
    float4* orow     = reinterpret_cast<float4*>(out + (size_t)t * D);

    const int c = threadIdx.x;  // 0..255 -> column block of 4 within each 1024-wide stream
    float4 a0 = xr[0 * 256 + c];
    float4 a1 = xr[1 * 256 + c];
    float4 a2 = xr[2 * 256 + c];
    float4 a3 = xr[3 * 256 + c];

    float4 o;
    // stream 0
    o.x = fmaf(m0.x, a0.x, fmaf(m0.y, a1.x, fmaf(m0.z, a2.x, m0.w * a3.x)));
    o.y = fmaf(m0.x, a0.y, fmaf(m0.y, a1.y, fmaf(m0.z, a2.y, m0.w * a3.y)));
    o.z = fmaf(m0.x, a0.z, fmaf(m0.y, a1.z, fmaf(m0.z, a2.z, m0.w * a3.z)));
    o.w = fmaf(m0.x, a0.w, fmaf(m0.y, a1.w, fmaf(m0.z, a2.w, m0.w * a3.w)));
    orow[0 * 256 + c] = o;
    // stream 1
    o.x = fmaf(m1.x, a0.x, fmaf(m1.y, a1.x, fmaf(m1.z, a2.x, m1.w * a3.x)));
    o.y = fmaf(m1.x, a0.y, fmaf(m1.y, a1.y, fmaf(m1.z, a2.y, m1.w * a3.y)));
    o.z = fmaf(m1.x, a0.z, fmaf(m1.y, a1.z, fmaf(m1.z, a2.z, m1.w * a3.z)));
    o.w = fmaf(m1.x, a0.w, fmaf(m1.y, a1.w, fmaf(m1.z, a2.w, m1.w * a3.w)));
    orow[1 * 256 + c] = o;
    // stream 2
    o.x = fmaf(m2.x, a0.x, fmaf(m2.y, a1.x, fmaf(m2.z, a2.x, m2.w * a3.x)));
    o.y = fmaf(m2.x, a0.y, fmaf(m2.y, a1.y, fmaf(m2.z, a2.y, m2.w * a3.y)));
    o.z = fmaf(m2.x, a0.z, fmaf(m2.y, a1.z, fmaf(m2.z, a2.z, m2.w * a3.z)));
    o.w = fmaf(m2.x, a0.w, fmaf(m2.y, a1.w, fmaf(m2.z, a2.w, m2.w * a3.w)));
    orow[2 * 256 + c] = o;
    // stream 3
    o.x = fmaf(m3.x, a0.x, fmaf(m3.y, a1.x, fmaf(m3.z, a2.x, m3.w * a3.x)));
    o.y = fmaf(m3.x, a0.y, fmaf(m3.y, a1.y, fmaf(m3.z, a2.y, m3.w * a3.y)));
    o.z = fmaf(m3.x, a0.z, fmaf(m3.y, a1.z, fmaf(m3.z, a2.z, m3.w * a3.z)));
    o.w = fmaf(m3.x, a0.w, fmaf(m3.y, a1.w, fmaf(m3.z, a2.w, m3.w * a3.w)));
    orow[3 * 256 + c] = o;
}

// ---------------------------------------------------------------------------
extern "C" void kernel_launch(void* const* d_in, const int* in_sizes, int n_in,
                              void* d_out, int out_size)
{
    const float* x     = (const float*)d_in[0];
    const float* Wres  = (const float*)d_in[1];
    const float* Wpre  = (const float*)d_in[2];
    const float* Wpost = (const float*)d_in[3];
    const float* HresB = (const float*)d_in[4];
    const float* HpreB = (const float*)d_in[5];
    const float* HpostB= (const float*)d_in[6];
    const float* gate  = (const float*)d_in[7];
    float* out         = (float*)d_out;

    const int NT = in_sizes[0] / D;  // 16384 tokens (B*T)

    logits_kernel<<<NT / 16, 256>>>(x, Wres, Wpre, Wpost, NT);
    sinkhorn_kernel<<<(NT + 127) / 128, 128>>>(HresB, HpreB, HpostB, gate, NT);
    mix_kernel<<<NT, 256>>>(x, out);
}

// round 2
// speedup vs baseline: 1.4319x; 1.4319x over previous
#include <cuda_runtime.h>
#include <math.h>

#define D 4096
#define NK 24                 // 16 res + 4 pre + 4 post logits per token
#define NTOK_MAX 16384
#define TAU_INV 10.0f
#define RMS_EPS 1.1920929e-07f

// Scratch: logits laid out [k][token]; M laid out [token][16].
__device__ float g_logits[(NK + 1) * NTOK_MAX];
__device__ float g_M[NTOK_MAX * 16];

__device__ __forceinline__ float warpSum(float v) {
    v += __shfl_xor_sync(0xffffffffu, v, 16);
    v += __shfl_xor_sync(0xffffffffu, v, 8);
    v += __shfl_xor_sync(0xffffffffu, v, 4);
    v += __shfl_xor_sync(0xffffffffu, v, 2);
    v += __shfl_xor_sync(0xffffffffu, v, 1);
    return v;
}

// ---- packed f32x2 helpers (sm_103a double-pumped fp32) --------------------
typedef unsigned long long u64;

__device__ __forceinline__ u64 splat2(float f) {
    u64 r;
    asm("mov.b64 %0, {%1, %1};" : "=l"(r) : "r"(__float_as_uint(f)));
    return r;
}
__device__ __forceinline__ u64 pack2(float a, float b) {
    u64 r;
    asm("mov.b64 %0, {%1, %2};" : "=l"(r) : "r"(__float_as_uint(a)), "r"(__float_as_uint(b)));
    return r;
}
__device__ __forceinline__ u64 fma2(u64 a, u64 b, u64 c) {
    u64 d;
    asm("fma.rn.f32x2 %0, %1, %2, %3;" : "=l"(d) : "l"(a), "l"(b), "l"(c));
    return d;
}
__device__ __forceinline__ void unpack2(u64 v, float& lo, float& hi) {
    unsigned int a, b;
    asm("mov.b64 {%0, %1}, %2;" : "=r"(a), "=r"(b) : "l"(v));
    lo = __uint_as_float(a);
    hi = __uint_as_float(b);
}

// ---------------------------------------------------------------------------
// Kernel A: 24 raw dot products + sum of squares per token.
// CTA = 256 threads (8 warps), 16 tokens (2 groups of 8).
// Each token group is served by 4 warps; warp j handles k-rows [6j, 6j+6)
// as 3 k-PAIRS packed into f32x2 lanes. W staged in smem interleaved as
// (w[2p][d], w[2p+1][d], w[2p][d+1], w[2p+1][d+1]) so one LDS.128 yields
// two ready f32x2 multiplicands. x elements are splatted.
// Per warp per 128-float step: 8 LDG.128 (x), 6 LDS.128 (W), 96 fma.f32x2.
// ---------------------------------------------------------------------------
__global__ __launch_bounds__(256, 2) void logits_kernel(
    const float* __restrict__ x,
    const float* __restrict__ Wres,
    const float* __restrict__ Wpre,
    const float* __restrict__ Wpost,
    int NT)
{
    __shared__ float4 Wsm[12 * 256];  // [kpair p][dhalf] : 48KB

    const int tid  = threadIdx.x;
    const int lane = tid & 31;
    const int warp = tid >> 5;
    const int grp  = warp >> 2;       // token group within CTA (0/1)
    const int j    = warp & 3;        // k-slice: rows 6j..6j+5  (kpairs 3j..3j+2)
    const int t0   = blockIdx.x * 16 + grp * 8;   // 8 tokens per group

    const float4* __restrict__ x4 = reinterpret_cast<const float4*>(x) + (size_t)t0 * (D / 4);
    const ulonglong2* __restrict__ Wsm2 = reinterpret_cast<const ulonglong2*>(Wsm);

    u64 acc[3][8];                    // [p][token] f32x2 over (k=2P, k=2P+1)
#pragma unroll
    for (int p = 0; p < 3; ++p)
#pragma unroll
        for (int t = 0; t < 8; ++t) acc[p][t] = 0ULL;

    u64 ssp[4] = {0ULL, 0ULL, 0ULL, 0ULL};  // j==0: sumsq pairs (tokens 2m,2m+1)

    for (int c = 0; c < D / 512; ++c) {
        // ---- producer: stage interleaved k-pair W chunk into smem ----
#pragma unroll
        for (int n = 0; n < 6; ++n) {
            int i  = tid + n * 256;            // 0..1535
            int p  = i >> 7;                   // kpair 0..11
            int d4 = i & 127;                  // float4 index in chunk
            int k0 = 2 * p;
            const float* r0p;
            const float* r1p;
            if (k0 < 16)      { r0p = Wres  + (size_t)k0 * D;        r1p = r0p + D; }
            else if (k0 < 20) { r0p = Wpre  + (size_t)(k0 - 16) * D; r1p = r0p + D; }
            else              { r0p = Wpost + (size_t)(k0 - 20) * D; r1p = r0p + D; }
            float4 r0 = reinterpret_cast<const float4*>(r0p)[c * 128 + d4];
            float4 r1 = reinterpret_cast<const float4*>(r1p)[c * 128 + d4];
            Wsm[p * 256 + 2 * d4]     = make_float4(r0.x, r1.x, r0.y, r1.y);
            Wsm[p * 256 + 2 * d4 + 1] = make_float4(r0.z, r1.z, r0.w, r1.w);
        }
        __syncthreads();

        // ---- consumer ----
#pragma unroll
        for (int s = 0; s < 4; ++s) {
            const int q = s * 32 + lane;       // within-chunk float4 index

            // W for this warp's 3 k-pairs at 4 d-positions: 6 LDS.128
            ulonglong2 wa0 = Wsm2[(3 * j + 0) * 256 + 2 * q];
            ulonglong2 wb0 = Wsm2[(3 * j + 0) * 256 + 2 * q + 1];
            ulonglong2 wa1 = Wsm2[(3 * j + 1) * 256 + 2 * q];
            ulonglong2 wb1 = Wsm2[(3 * j + 1) * 256 + 2 * q + 1];
            ulonglong2 wa2 = Wsm2[(3 * j + 2) * 256 + 2 * q];
            ulonglong2 wb2 = Wsm2[(3 * j + 2) * 256 + 2 * q + 1];

            // x: 8 tokens, batched loads for MLP
            float4 a[8];
#pragma unroll
            for (int t = 0; t < 8; ++t)
                a[t] = x4[(size_t)t * (D / 4) + c * 128 + q];

#pragma unroll
            for (int t = 0; t < 8; ++t) {
                u64 s0 = splat2(a[t].x);
                u64 s1 = splat2(a[t].y);
                u64 s2 = splat2(a[t].z);
                u64 s3 = splat2(a[t].w);
                acc[0][t] = fma2(s0, wa0.x, acc[0][t]);
                acc[0][t] = fma2(s1, wa0.y, acc[0][t]);
                acc[0][t] = fma2(s2, wb0.x, acc[0][t]);
                acc[0][t] = fma2(s3, wb0.y, acc[0][t]);
                acc[1][t] = fma2(s0, wa1.x, acc[1][t]);
                acc[1][t] = fma2(s1, wa1.y, acc[1][t]);
                acc[1][t] = fma2(s2, wb1.x, acc[1][t]);
                acc[1][t] = fma2(s3, wb1.y, acc[1][t]);
                acc[2][t] = fma2(s0, wa2.x, acc[2][t]);
                acc[2][t] = fma2(s1, wa2.y, acc[2][t]);
                acc[2][t] = fma2(s2, wb2.x, acc[2][t]);
                acc[2][t] = fma2(s3, wb2.y, acc[2][t]);
            }

            if (j == 0) {
#pragma unroll
                for (int m = 0; m < 4; ++m) {
                    u64 px = pack2(a[2 * m].x, a[2 * m + 1].x);
                    u64 py = pack2(a[2 * m].y, a[2 * m + 1].y);
                    u64 pz = pack2(a[2 * m].z, a[2 * m + 1].z);
                    u64 pw = pack2(a[2 * m].w, a[2 * m + 1].w);
                    ssp[m] = fma2(px, px, ssp[m]);
                    ssp[m] = fma2(py, py, ssp[m]);
                    ssp[m] = fma2(pz, pz, ssp[m]);
                    ssp[m] = fma2(pw, pw, ssp[m]);
                }
            }
        }
        __syncthreads();
    }

    // ---- reduce & store ----
#pragma unroll
    for (int p = 0; p < 3; ++p) {
#pragma unroll
        for (int t = 0; t < 8; ++t) {
            float v0, v1;
            unpack2(acc[p][t], v0, v1);
            v0 = warpSum(v0);
            v1 = warpSum(v1);
            if (lane == 0) {
                int k = 6 * j + 2 * p;
                g_logits[(size_t)k * NT + t0 + t]       = v0;
                g_logits[(size_t)(k + 1) * NT + t0 + t] = v1;
            }
        }
    }
    if (j == 0) {
#pragma unroll
        for (int m = 0; m < 4; ++m) {
            float v0, v1;
            unpack2(ssp[m], v0, v1);
            v0 = warpSum(v0);
            v1 = warpSum(v1);
            if (lane == 0) {
                g_logits[(size_t)NK * NT + t0 + 2 * m]     = v0;
                g_logits[(size_t)NK * NT + t0 + 2 * m + 1] = v1;
            }
        }
    }
}

// ---------------------------------------------------------------------------
// Kernel A2: per-token RMS scale, Sinkhorn(50 iters), softmaxes, gate -> M.
// Fast-math MUFU exp/log (error budget 1e-3 >> ~1e-6 introduced).
// ---------------------------------------------------------------------------
__global__ __launch_bounds__(128) void sinkhorn_kernel(
    const float* __restrict__ HresB,
    const float* __restrict__ HpreB,
    const float* __restrict__ HpostB,
    const float* __restrict__ gate,
    int NT)
{
    int t = blockIdx.x * 128 + threadIdx.x;
    if (t >= NT) return;

    float ss  = g_logits[(size_t)NK * NT + t];
    float rms = rsqrtf(ss * (1.0f / (float)D) + RMS_EPS);

    float Z[16];
#pragma unroll
    for (int ij = 0; ij < 16; ++ij)
        Z[ij] = (HresB[ij] + g_logits[(size_t)ij * NT + t] * rms) * TAU_INV;

    float pre[4], post[4];
#pragma unroll
    for (int i = 0; i < 4; ++i) {
        pre[i]  = HpreB[i]  + g_logits[(size_t)(16 + i) * NT + t] * rms;
        post[i] = HpostB[i] + g_logits[(size_t)(20 + i) * NT + t] * rms;
    }

    float u[4] = {0.f, 0.f, 0.f, 0.f};
    float v[4] = {0.f, 0.f, 0.f, 0.f};
#pragma unroll 1
    for (int it = 0; it < 50; ++it) {
#pragma unroll
        for (int i = 0; i < 4; ++i) {
            float a0 = Z[i * 4 + 0] + v[0];
            float a1 = Z[i * 4 + 1] + v[1];
            float a2 = Z[i * 4 + 2] + v[2];
            float a3 = Z[i * 4 + 3] + v[3];
            float m = fmaxf(fmaxf(a0, a1), fmaxf(a2, a3));
            float sE = __expf(a0 - m) + __expf(a1 - m) + __expf(a2 - m) + __expf(a3 - m);
            u[i] = -(m + __logf(sE));
        }
#pragma unroll
        for (int jj = 0; jj < 4; ++jj) {
            float a0 = Z[0 * 4 + jj] + u[0];
            float a1 = Z[1 * 4 + jj] + u[1];
            float a2 = Z[2 * 4 + jj] + u[2];
            float a3 = Z[3 * 4 + jj] + u[3];
            float m = fmaxf(fmaxf(a0, a1), fmaxf(a2, a3));
            float sE = __expf(a0 - m) + __expf(a1 - m) + __expf(a2 - m) + __expf(a3 - m);
            v[jj] = -(m + __logf(sE));
        }
    }

    {
        float m = fmaxf(fmaxf(pre[0], pre[1]), fmaxf(pre[2], pre[3]));
        float e0 = __expf(pre[0] - m), e1 = __expf(pre[1] - m);
        float e2 = __expf(pre[2] - m), e3 = __expf(pre[3] - m);
        float inv = 1.0f / (e0 + e1 + e2 + e3);
        pre[0] = e0 * inv; pre[1] = e1 * inv; pre[2] = e2 * inv; pre[3] = e3 * inv;
    }
    {
        float m = fmaxf(fmaxf(post[0], post[1]), fmaxf(post[2], post[3]));
        float e0 = __expf(post[0] - m), e1 = __expf(post[1] - m);
        float e2 = __expf(post[2] - m), e3 = __expf(post[3] - m);
        float inv = 1.0f / (e0 + e1 + e2 + e3);
        post[0] = e0 * inv; post[1] = e1 * inv; post[2] = e2 * inv; post[3] = e3 * inv;
    }

    float g = 1.0f / (1.0f + __expf(-gate[0]));
    float M[16];
#pragma unroll
    for (int i = 0; i < 4; ++i) {
#pragma unroll
        for (int jj = 0; jj < 4; ++jj) {
            float hres = __expf(Z[i * 4 + jj] + u[i] + v[jj]);
            float mg   = g * hres + ((i == jj) ? (1.0f - g) : 0.0f);
            M[i * 4 + jj] = mg + post[i] * pre[jj];
        }
    }

    float4* mp = reinterpret_cast<float4*>(g_M + (size_t)t * 16);
    mp[0] = make_float4(M[0],  M[1],  M[2],  M[3]);
    mp[1] = make_float4(M[4],  M[5],  M[6],  M[7]);
    mp[2] = make_float4(M[8],  M[9],  M[10], M[11]);
    mp[3] = make_float4(M[12], M[13], M[14], M[15]);
}

// ---------------------------------------------------------------------------
// Kernel B: out_row = M @ x_streams. One CTA per token, pure streaming.
// ---------------------------------------------------------------------------
__global__ __launch_bounds__(256) void mix_kernel(
    const float* __restrict__ x,
    float* __restrict__ out)
{
    const int t = blockIdx.x;
    const float4* Mr = reinterpret_cast<const float4*>(g_M + (size_t)t * 16);
    const float4 m0 = Mr[0];
    const float4 m1 = Mr[1];
    const float4 m2 = Mr[2];
    const float4 m3 = Mr[3];

    const float4* xr = reinterpret_cast<const float4*>(x + (size_t)t * D);
    float4* orow     = reinterpret_cast<float4*>(out + (size_t)t * D);

    const int c = threadIdx.x;
    float4 a0 = xr[0 * 256 + c];
    float4 a1 = xr[1 * 256 + c];
    float4 a2 = xr[2 * 256 + c];
    float4 a3 = xr[3 * 256 + c];

    float4 o;
    o.x = fmaf(m0.x, a0.x, fmaf(m0.y, a1.x, fmaf(m0.z, a2.x, m0.w * a3.x)));
    o.y = fmaf(m0.x, a0.y, fmaf(m0.y, a1.y, fmaf(m0.z, a2.y, m0.w * a3.y)));
    o.z = fmaf(m0.x, a0.z, fmaf(m0.y, a1.z, fmaf(m0.z, a2.z, m0.w * a3.z)));
    o.w = fmaf(m0.x, a0.w, fmaf(m0.y, a1.w, fmaf(m0.z, a2.w, m0.w * a3.w)));
    orow[0 * 256 + c] = o;
    o.x = fmaf(m1.x, a0.x, fmaf(m1.y, a1.x, fmaf(m1.z, a2.x, m1.w * a3.x)));
    o.y = fmaf(m1.x, a0.y, fmaf(m1.y, a1.y, fmaf(m1.z, a2.y, m1.w * a3.y)));
    o.z = fmaf(m1.x, a0.z, fmaf(m1.y, a1.z, fmaf(m1.z, a2.z, m1.w * a3.z)));
    o.w = fmaf(m1.x, a0.w, fmaf(m1.y, a1.w, fmaf(m1.z, a2.w, m1.w * a3.w)));
    orow[1 * 256 + c] = o;
    o.x = fmaf(m2.x, a0.x, fmaf(m2.y, a1.x, fmaf(m2.z, a2.x, m2.w * a3.x)));
    o.y = fmaf(m2.x, a0.y, fmaf(m2.y, a1.y, fmaf(m2.z, a2.y, m2.w * a3.y)));
    o.z = fmaf(m2.x, a0.z, fmaf(m2.y, a1.z, fmaf(m2.z, a2.z, m2.w * a3.z)));
    o.w = fmaf(m2.x, a0.w, fmaf(m2.y, a1.w, fmaf(m2.z, a2.w, m2.w * a3.w)));
    orow[2 * 256 + c] = o;
    o.x = fmaf(m3.x, a0.x, fmaf(m3.y, a1.x, fmaf(m3.z, a2.x, m3.w * a3.x)));
    o.y = fmaf(m3.x, a0.y, fmaf(m3.y, a1.y, fmaf(m3.z, a2.y, m3.w * a3.y)));
    o.z = fmaf(m3.x, a0.z, fmaf(m3.y, a1.z, fmaf(m3.z, a2.z, m3.w * a3.z)));
    o.w = fmaf(m3.x, a0.w, fmaf(m3.y, a1.w, fmaf(m3.z, a2.w, m3.w * a3.w)));
    orow[3 * 256 + c] = o;
}

// ---------------------------------------------------------------------------
extern "C" void kernel_launch(void* const* d_in, const int* in_sizes, int n_in,
                              void* d_out, int out_size)
{
    const float* x     = (const float*)d_in[0];
    const float* Wres  = (const float*)d_in[1];
    const float* Wpre  = (const float*)d_in[2];
    const float* Wpost = (const float*)d_in[3];
    const float* HresB = (const float*)d_in[4];
    const float* HpreB = (const float*)d_in[5];
    const float* HpostB= (const float*)d_in[6];
    const float* gate  = (const float*)d_in[7];
    float* out         = (float*)d_out;

    const int NT = in_sizes[0] / D;  // 16384 tokens

    logits_kernel<<<NT / 16, 256>>>(x, Wres, Wpre, Wpost, NT);
    sinkhorn_kernel<<<(NT + 127) / 128, 128>>>(HresB, HpreB, HpostB, gate, NT);
    mix_kernel<<<NT, 256>>>(x, out);
}